// round 4
// baseline (speedup 1.0000x reference)
#include <cuda_runtime.h>
#include <cstdint>

// Problem constants
#define BH_  64
#define S_   1024
#define D_   64
#define QT   32      // queries per CTA
#define KC   128     // keys per pipeline chunk
#define NCH  (S_/KC) // 8 chunks
#define NTHREADS 256

// smem strides (floats), chosen for bank-conflict-free mma fragment access
#define PADK 68
#define PADV 72
#define PADS 1032

// smem layout (float offsets)
#define OFF_Q  0
#define SZ_Q   (QT*PADK)
#define OFF_KV (OFF_Q + SZ_Q)
#define SZ_KV  (2*KC*PADV)
#define OFF_S  (OFF_KV + SZ_KV)
#define SZ_S   (QT*PADS)
#define OFF_M  (OFF_S + SZ_S)
#define SMEM_FLOATS (OFF_M + S_)
#define SMEM_BYTES  (SMEM_FLOATS * 4)   // 218624 B < 227 KB

__device__ __forceinline__ unsigned f2tf(float x) {
    unsigned r;
    asm("cvt.rna.tf32.f32 %0, %1;" : "=r"(r) : "f"(x));
    return r;
}

__device__ __forceinline__ void mma8(float* c, const unsigned* a, unsigned b0, unsigned b1) {
    asm volatile(
        "mma.sync.aligned.m16n8k8.row.col.f32.tf32.tf32.f32 "
        "{%0,%1,%2,%3},{%4,%5,%6,%7},{%8,%9},{%0,%1,%2,%3};\n"
        : "+f"(c[0]), "+f"(c[1]), "+f"(c[2]), "+f"(c[3])
        : "r"(a[0]), "r"(a[1]), "r"(a[2]), "r"(a[3]), "r"(b0), "r"(b1));
}

__device__ __forceinline__ void cpasync16(float* smem_dst, const float* gsrc) {
    unsigned d = (unsigned)__cvta_generic_to_shared(smem_dst);
    asm volatile("cp.async.cg.shared.global [%0],[%1],16;\n" :: "r"(d), "l"(gsrc));
}
#define CP_COMMIT() asm volatile("cp.async.commit_group;\n" ::: "memory")
#define CP_WAIT1()  asm volatile("cp.async.wait_group 1;\n" ::: "memory")

__global__ void __launch_bounds__(NTHREADS, 1)
attn_kernel(const float* __restrict__ Q, const float* __restrict__ K,
            const float* __restrict__ V, const int* __restrict__ M,
            float* __restrict__ Out, float* __restrict__ Attn)
{
    extern __shared__ float sm[];
    float* sQ  = sm + OFF_Q;
    float* sKV = sm + OFF_KV;   // two buffers of KC*PADV floats each
    float* sS  = sm + OFF_S;    // 32 x 1024 score block (padded stride)
    int*   sM  = (int*)(sm + OFF_M);

    const int bh   = blockIdx.y;
    const int q0   = blockIdx.x * QT;
    const int tid  = threadIdx.x;
    const int lane = tid & 31;
    const int warp = tid >> 5;

    const float* gQ = Q + ((size_t)bh * S_ + q0) * D_;
    const float* gK = K + (size_t)bh * S_ * D_;
    const float* gV = V + (size_t)bh * S_ * D_;
    const int*   gM = M + bh * S_;
    float* gO = Out + ((size_t)bh * S_ + q0) * D_;
    float* gA = Attn ? (Attn + ((size_t)bh * S_ + q0) * S_) : nullptr;

    // ---- stage Q tile + mask into smem ----
    for (int i = tid; i < QT * D_ / 4; i += NTHREADS) {
        int row = i >> 4, c4 = i & 15;   // 16 float4 per row of 64 floats
        float4 val = reinterpret_cast<const float4*>(gQ)[row * (D_ / 4) + c4];
        *reinterpret_cast<float4*>(sQ + row * PADK + c4 * 4) = val;  // 272-byte stride, 16B aligned
    }
    for (int i = tid; i < S_; i += NTHREADS) sM[i] = gM[i];

    // ---- prologue: K chunks 0,1 via cp.async (double buffer) ----
    #pragma unroll
    for (int b = 0; b < 2; b++) {
        const float* src = gK + (size_t)b * KC * D_;
        float* dst = sKV + b * KC * PADV;
        #pragma unroll
        for (int j = 0; j < 8; j++) {
            int f = j * NTHREADS + tid;
            int row = f >> 4, c4 = f & 15;
            cpasync16(dst + row * PADK + c4 * 4, src + row * D_ + c4 * 4);
        }
        CP_COMMIT();
    }
    __syncthreads();   // sQ, sM visible to all

    // ---- preload Q (A) fragments in tf32, reused for the whole kernel ----
    const int qb = (warp >> 2) * 16;   // warp m-tile: rows qb..qb+15
    const int wk = warp & 3;           // warp n-tile in QK: keys wk*32..wk*32+31
    unsigned afr[8][4];
    #pragma unroll
    for (int ks = 0; ks < 8; ks++) {
        int r0 = qb + (lane >> 2);
        int c0 = (lane & 3) + ks * 8;
        afr[ks][0] = f2tf(sQ[r0 * PADK + c0]);
        afr[ks][1] = f2tf(sQ[(r0 + 8) * PADK + c0]);
        afr[ks][2] = f2tf(sQ[r0 * PADK + c0 + 4]);
        afr[ks][3] = f2tf(sQ[(r0 + 8) * PADK + c0 + 4]);
    }

    // ---- QK^T: stream K chunks, scores -> smem ----
    for (int c = 0; c < NCH; c++) {
        CP_WAIT1();
        __syncthreads();
        const float* sK = sKV + (c & 1) * KC * PADV;  // stored with PADK stride

        float acc[4][4];
        #pragma unroll
        for (int nt = 0; nt < 4; nt++) { acc[nt][0] = acc[nt][1] = acc[nt][2] = acc[nt][3] = 0.f; }

        #pragma unroll
        for (int ks = 0; ks < 8; ks++) {
            #pragma unroll
            for (int nt = 0; nt < 4; nt++) {
                int key = wk * 32 + nt * 8 + (lane >> 2);
                int d0  = (lane & 3) + ks * 8;
                unsigned b0 = f2tf(sK[key * PADK + d0]);
                unsigned b1 = f2tf(sK[key * PADK + d0 + 4]);
                mma8(acc[nt], afr[ks], b0, b1);
            }
        }
        #pragma unroll
        for (int nt = 0; nt < 4; nt++) {
            int col = c * KC + wk * 32 + nt * 8 + 2 * (lane & 3);
            int r0  = qb + (lane >> 2);
            *reinterpret_cast<float2*>(&sS[r0 * PADS + col])       = make_float2(acc[nt][0], acc[nt][1]);
            *reinterpret_cast<float2*>(&sS[(r0 + 8) * PADS + col]) = make_float2(acc[nt][2], acc[nt][3]);
        }
        __syncthreads();   // all reads of buf done before refill
        if (c + 2 < NCH) {
            const float* src = gK + (size_t)(c + 2) * KC * D_;
            float* dst = sKV + (c & 1) * KC * PADV;
            #pragma unroll
            for (int j = 0; j < 8; j++) {
                int f = j * NTHREADS + tid;
                int row = f >> 4, c4 = f & 15;
                cpasync16(dst + row * PADK + c4 * 4, src + row * D_ + c4 * 4);
            }
        }
        CP_COMMIT();       // keep group count consistent (may be empty)
    }

    // ---- prologue: V chunks 0,1 (loads overlap softmax below) ----
    #pragma unroll
    for (int b = 0; b < 2; b++) {
        const float* src = gV + (size_t)b * KC * D_;
        float* dst = sKV + b * KC * PADV;
        #pragma unroll
        for (int j = 0; j < 8; j++) {
            int f = j * NTHREADS + tid;
            int row = f >> 4, c4 = f & 15;
            cpasync16(dst + row * PADV + c4 * 4, src + row * D_ + c4 * 4);
        }
        CP_COMMIT();
    }

    // ---- masked softmax over each of this tile's 32 rows; write attn ----
    {
        const int r   = warp * 4 + (lane >> 3);  // 8 lanes per row
        const int sub = lane & 7;
        const float CEXP = 0.125f * 1.44269504088896340736f;  // (1/T)*log2(e)
        float4* rowS = reinterpret_cast<float4*>(sS + (size_t)r * PADS);
        const int4* m4 = reinterpret_cast<const int4*>(sM);

        float mx = -1e30f;
        #pragma unroll 4
        for (int j = 0; j < 32; j++) {
            int i4 = sub + j * 8;
            int4 mk = m4[i4];
            float4 s = rowS[i4];
            if (mk.x) mx = fmaxf(mx, s.x);
            if (mk.y) mx = fmaxf(mx, s.y);
            if (mk.z) mx = fmaxf(mx, s.z);
            if (mk.w) mx = fmaxf(mx, s.w);
        }
        mx = fmaxf(mx, __shfl_xor_sync(0xffffffffu, mx, 1));
        mx = fmaxf(mx, __shfl_xor_sync(0xffffffffu, mx, 2));
        mx = fmaxf(mx, __shfl_xor_sync(0xffffffffu, mx, 4));
        bool any = (mx > -1e29f);

        float l = 0.f;
        #pragma unroll 4
        for (int j = 0; j < 32; j++) {
            int i4 = sub + j * 8;
            int4 mk = m4[i4];
            float4 s = rowS[i4];
            float4 p;
            p.x = mk.x ? exp2f((s.x - mx) * CEXP) : 0.f;
            p.y = mk.y ? exp2f((s.y - mx) * CEXP) : 0.f;
            p.z = mk.z ? exp2f((s.z - mx) * CEXP) : 0.f;
            p.w = mk.w ? exp2f((s.w - mx) * CEXP) : 0.f;
            rowS[i4] = p;
            l += p.x + p.y + p.z + p.w;
        }
        l += __shfl_xor_sync(0xffffffffu, l, 1);
        l += __shfl_xor_sync(0xffffffffu, l, 2);
        l += __shfl_xor_sync(0xffffffffu, l, 4);

        float invl = any ? (1.f / l) : 0.f;
        const float uni = 1.f / 1024.f;   // reference: all-masked row -> uniform
        float4* rowA = gA ? reinterpret_cast<float4*>(gA + (size_t)r * S_) : nullptr;
        #pragma unroll 4
        for (int j = 0; j < 32; j++) {
            int i4 = sub + j * 8;
            float4 p = rowS[i4];
            if (any) { p.x *= invl; p.y *= invl; p.z *= invl; p.w *= invl; }
            else     { p.x = p.y = p.z = p.w = uni; }
            rowS[i4] = p;              // normalized P for PV
            if (rowA) rowA[i4] = p;    // attn output
        }
    }
    // (PV loop's wait+syncthreads provides the barrier before cross-warp P reads)

    // ---- P @ V: stream V chunks ----
    const int nb = (warp & 3) * 16;   // output d-columns nb..nb+15
    float o0[4] = {0.f, 0.f, 0.f, 0.f};
    float o1[4] = {0.f, 0.f, 0.f, 0.f};
    for (int c = 0; c < NCH; c++) {
        CP_WAIT1();
        __syncthreads();
        const float* sV = sKV + (c & 1) * KC * PADV;
        #pragma unroll
        for (int ks = 0; ks < 16; ks++) {
            unsigned a[4];
            int r0 = qb + (lane >> 2);
            int kc = c * KC + ks * 8 + (lane & 3);
            a[0] = f2tf(sS[r0 * PADS + kc]);
            a[1] = f2tf(sS[(r0 + 8) * PADS + kc]);
            a[2] = f2tf(sS[r0 * PADS + kc + 4]);
            a[3] = f2tf(sS[(r0 + 8) * PADS + kc + 4]);
            int key = ks * 8 + (lane & 3);
            int dc0 = nb + (lane >> 2);
            unsigned b0 = f2tf(sV[key * PADV + dc0]);
            unsigned b1 = f2tf(sV[(key + 4) * PADV + dc0]);
            mma8(o0, a, b0, b1);
            unsigned b2 = f2tf(sV[key * PADV + dc0 + 8]);
            unsigned b3 = f2tf(sV[(key + 4) * PADV + dc0 + 8]);
            mma8(o1, a, b2, b3);
        }
        __syncthreads();
        if (c + 2 < NCH) {
            const float* src = gV + (size_t)(c + 2) * KC * D_;
            float* dst = sKV + (c & 1) * KC * PADV;
            #pragma unroll
            for (int j = 0; j < 8; j++) {
                int f = j * NTHREADS + tid;
                int row = f >> 4, c4 = f & 15;
                cpasync16(dst + row * PADV + c4 * 4, src + row * D_ + c4 * 4);
            }
        }
        CP_COMMIT();
    }

    // ---- write output tile ----
    {
        int r0  = qb + (lane >> 2);
        int col = nb + 2 * (lane & 3);
        *reinterpret_cast<float2*>(&gO[(size_t)r0 * D_ + col])           = make_float2(o0[0], o0[1]);
        *reinterpret_cast<float2*>(&gO[(size_t)(r0 + 8) * D_ + col])     = make_float2(o0[2], o0[3]);
        *reinterpret_cast<float2*>(&gO[(size_t)r0 * D_ + col + 8])       = make_float2(o1[0], o1[1]);
        *reinterpret_cast<float2*>(&gO[(size_t)(r0 + 8) * D_ + col + 8]) = make_float2(o1[2], o1[3]);
    }
}

extern "C" void kernel_launch(void* const* d_in, const int* in_sizes, int n_in,
                              void* d_out, int out_size)
{
    const float* q    = (const float*)d_in[0];
    const float* k    = (const float*)d_in[1];
    const float* v    = (const float*)d_in[2];
    const int*   mask = (const int*)d_in[3];
    float* out = (float*)d_out;

    const size_t out_elems  = (size_t)BH_ * S_ * D_;   //  4,194,304
    const size_t attn_elems = (size_t)BH_ * S_ * S_;   // 67,108,864
    // Output tuple layout: [output, attn]. Only write attn if the buffer holds it.
    float* attn = ((size_t)out_size >= out_elems + attn_elems) ? (out + out_elems) : nullptr;

    cudaFuncSetAttribute(attn_kernel, cudaFuncAttributeMaxDynamicSharedMemorySize, SMEM_BYTES);

    dim3 grid(S_ / QT, BH_);
    attn_kernel<<<grid, NTHREADS, SMEM_BYTES>>>(q, k, v, mask, out, attn);
}

// round 5
// speedup vs baseline: 1.1453x; 1.1453x over previous
#include <cuda_runtime.h>
#include <cstdint>

// Problem constants
#define BH_  64
#define S_   1024
#define D_   64
#define QT   32      // queries per CTA
#define KC   128     // keys per pipeline chunk
#define NCH  (S_/KC) // 8 chunks
#define NTHREADS 512

// smem strides (floats)
#define PADK 68      // K/Q rows: QK B-loads conflict-free
#define PADV 72      // V rows:   PV B-loads conflict-free
#define PADS 1028    // score rows: PV A-loads conflict-free

// smem layout (float offsets)
#define OFF_Q  0
#define SZ_Q   (QT*PADK)            // 2176 floats (reused as PV reduction buffer)
#define OFF_KV (OFF_Q + SZ_Q)
#define SZ_KV  (2*KC*PADV)          // 18432
#define OFF_S  (OFF_KV + SZ_KV)
#define SZ_S   (QT*PADS)            // 32896
#define OFF_M  (OFF_S + SZ_S)       // mask: 1024 ints
#define OFF_INV (OFF_M + S_)        // 32 floats
#define SMEM_FLOATS (OFF_INV + 32)
#define SMEM_BYTES  (SMEM_FLOATS * 4)   // 218368 B < 227 KB

__device__ __forceinline__ unsigned f2tf(float x) {
    unsigned r;
    asm("cvt.rna.tf32.f32 %0, %1;" : "=r"(r) : "f"(x));
    return r;
}

__device__ __forceinline__ void mma8(float* c, const unsigned* a, unsigned b0, unsigned b1) {
    asm volatile(
        "mma.sync.aligned.m16n8k8.row.col.f32.tf32.tf32.f32 "
        "{%0,%1,%2,%3},{%4,%5,%6,%7},{%8,%9},{%0,%1,%2,%3};\n"
        : "+f"(c[0]), "+f"(c[1]), "+f"(c[2]), "+f"(c[3])
        : "r"(a[0]), "r"(a[1]), "r"(a[2]), "r"(a[3]), "r"(b0), "r"(b1));
}

__device__ __forceinline__ void cpasync16(float* smem_dst, const float* gsrc) {
    unsigned d = (unsigned)__cvta_generic_to_shared(smem_dst);
    asm volatile("cp.async.cg.shared.global [%0],[%1],16;\n" :: "r"(d), "l"(gsrc));
}
#define CP_COMMIT() asm volatile("cp.async.commit_group;\n" ::: "memory")
#define CP_WAIT1()  asm volatile("cp.async.wait_group 1;\n" ::: "memory")

__global__ void __launch_bounds__(NTHREADS, 1)
attn_kernel(const float* __restrict__ Q, const float* __restrict__ K,
            const float* __restrict__ V, const int* __restrict__ M,
            float* __restrict__ Out, float* __restrict__ Attn)
{
    extern __shared__ float sm[];
    float* sQ   = sm + OFF_Q;
    float* sKV  = sm + OFF_KV;   // two buffers of KC*PADV floats each
    float* sS   = sm + OFF_S;    // 32 x 1024 score block (padded stride)
    int*   sM   = (int*)(sm + OFF_M);
    float* sInv = sm + OFF_INV;

    const int bh   = blockIdx.y;
    const int q0   = blockIdx.x * QT;
    const int tid  = threadIdx.x;
    const int lane = tid & 31;
    const int warp = tid >> 5;   // 0..15

    const float* gQ = Q + ((size_t)bh * S_ + q0) * D_;
    const float* gK = K + (size_t)bh * S_ * D_;
    const float* gV = V + (size_t)bh * S_ * D_;
    const int*   gM = M + bh * S_;
    float* gO = Out + ((size_t)bh * S_ + q0) * D_;
    float* gA = Attn ? (Attn + ((size_t)bh * S_ + q0) * S_) : nullptr;

    // ---- stage Q tile + mask into smem ----
    {
        int i = tid;                       // 32*16 = 512 float4s, one per thread
        int row = i >> 4, c4 = i & 15;
        float4 val = reinterpret_cast<const float4*>(gQ)[row * (D_ / 4) + c4];
        *reinterpret_cast<float4*>(sQ + row * PADK + c4 * 4) = val;
    }
    for (int i = tid; i < S_; i += NTHREADS) sM[i] = gM[i];

    // ---- prologue: K chunks 0,1 via cp.async (double buffer) ----
    #pragma unroll
    for (int b = 0; b < 2; b++) {
        const float* src = gK + (size_t)b * KC * D_;
        float* dst = sKV + b * KC * PADV;
        #pragma unroll
        for (int j = 0; j < 4; j++) {      // 128*16 = 2048 float4s / 512 thr
            int f = j * NTHREADS + tid;
            int row = f >> 4, c4 = f & 15;
            cpasync16(dst + row * PADK + c4 * 4, src + row * D_ + c4 * 4);
        }
        CP_COMMIT();
    }
    __syncthreads();   // sQ, sM visible to all

    // ---- preload Q (A) fragments in tf32, reused for the whole kernel ----
    const int qb = (warp >> 3) * 16;   // m-tile rows qb..qb+15 (2 groups of 8 warps)
    unsigned afr[8][4];
    #pragma unroll
    for (int ks = 0; ks < 8; ks++) {
        int r0 = qb + (lane >> 2);
        int c0 = (lane & 3) + ks * 8;
        afr[ks][0] = f2tf(sQ[r0 * PADK + c0]);
        afr[ks][1] = f2tf(sQ[(r0 + 8) * PADK + c0]);
        afr[ks][2] = f2tf(sQ[r0 * PADK + c0 + 4]);
        afr[ks][3] = f2tf(sQ[(r0 + 8) * PADK + c0 + 4]);
    }

    // ---- QK^T: stream K chunks, scores -> smem ----
    // Warp layout: wm = warp>>3 (rows), wn = warp&7 (keys wn*16..wn*16+15)
    const int wn = warp & 7;
    for (int c = 0; c < NCH; c++) {
        CP_WAIT1();
        __syncthreads();
        const float* sK = sKV + (c & 1) * KC * PADV;  // stored with PADK stride

        float acc[2][4];
        #pragma unroll
        for (int nt = 0; nt < 2; nt++) { acc[nt][0] = acc[nt][1] = acc[nt][2] = acc[nt][3] = 0.f; }

        #pragma unroll
        for (int ks = 0; ks < 8; ks++) {
            #pragma unroll
            for (int nt = 0; nt < 2; nt++) {
                int key = wn * 16 + nt * 8 + (lane >> 2);
                int d0  = (lane & 3) + ks * 8;
                unsigned b0 = f2tf(sK[key * PADK + d0]);
                unsigned b1 = f2tf(sK[key * PADK + d0 + 4]);
                mma8(acc[nt], afr[ks], b0, b1);
            }
        }
        #pragma unroll
        for (int nt = 0; nt < 2; nt++) {
            int col = c * KC + wn * 16 + nt * 8 + 2 * (lane & 3);
            int r0  = qb + (lane >> 2);
            *reinterpret_cast<float2*>(&sS[r0 * PADS + col])       = make_float2(acc[nt][0], acc[nt][1]);
            *reinterpret_cast<float2*>(&sS[(r0 + 8) * PADS + col]) = make_float2(acc[nt][2], acc[nt][3]);
        }
        __syncthreads();   // all reads of buf done before refill
        if (c + 2 < NCH) {
            const float* src = gK + (size_t)(c + 2) * KC * D_;
            float* dst = sKV + (c & 1) * KC * PADV;
            #pragma unroll
            for (int j = 0; j < 4; j++) {
                int f = j * NTHREADS + tid;
                int row = f >> 4, c4 = f & 15;
                cpasync16(dst + row * PADK + c4 * 4, src + row * D_ + c4 * 4);
            }
        }
        CP_COMMIT();       // keep group count consistent (may be empty)
    }

    // ---- prologue: V chunks 0,1 (loads overlap softmax below) ----
    #pragma unroll
    for (int b = 0; b < 2; b++) {
        const float* src = gV + (size_t)b * KC * D_;
        float* dst = sKV + b * KC * PADV;
        #pragma unroll
        for (int j = 0; j < 4; j++) {
            int f = j * NTHREADS + tid;
            int row = f >> 4, c4 = f & 15;
            cpasync16(dst + row * PADV + c4 * 4, src + row * D_ + c4 * 4);
        }
        CP_COMMIT();
    }

    // ---- masked softmax over 32 rows (16 lanes/row); attn -> gmem,
    //      UNNORMALIZED p kept in sS, invl stored in sInv ----
    {
        const int r   = tid >> 4;         // 0..31
        const int sub = tid & 15;
        const float CEXP = 0.125f * 1.44269504088896340736f;  // (1/T)*log2(e)
        float4* rowS = reinterpret_cast<float4*>(sS + (size_t)r * PADS);
        const int4* m4 = reinterpret_cast<const int4*>(sM);

        float mx = -1e30f;
        #pragma unroll 4
        for (int j = 0; j < 16; j++) {
            int i4 = sub + j * 16;
            int4 mk = m4[i4];
            float4 s = rowS[i4];
            if (mk.x) mx = fmaxf(mx, s.x);
            if (mk.y) mx = fmaxf(mx, s.y);
            if (mk.z) mx = fmaxf(mx, s.z);
            if (mk.w) mx = fmaxf(mx, s.w);
        }
        mx = fmaxf(mx, __shfl_xor_sync(0xffffffffu, mx, 1));
        mx = fmaxf(mx, __shfl_xor_sync(0xffffffffu, mx, 2));
        mx = fmaxf(mx, __shfl_xor_sync(0xffffffffu, mx, 4));
        mx = fmaxf(mx, __shfl_xor_sync(0xffffffffu, mx, 8));
        bool any = (mx > -1e29f);

        float l = 0.f;
        #pragma unroll 4
        for (int j = 0; j < 16; j++) {
            int i4 = sub + j * 16;
            int4 mk = m4[i4];
            float4 s = rowS[i4];
            float4 p;
            p.x = mk.x ? exp2f((s.x - mx) * CEXP) : 0.f;
            p.y = mk.y ? exp2f((s.y - mx) * CEXP) : 0.f;
            p.z = mk.z ? exp2f((s.z - mx) * CEXP) : 0.f;
            p.w = mk.w ? exp2f((s.w - mx) * CEXP) : 0.f;
            rowS[i4] = p;
            l += p.x + p.y + p.z + p.w;
        }
        l += __shfl_xor_sync(0xffffffffu, l, 1);
        l += __shfl_xor_sync(0xffffffffu, l, 2);
        l += __shfl_xor_sync(0xffffffffu, l, 4);
        l += __shfl_xor_sync(0xffffffffu, l, 8);

        float invl = any ? (1.f / l) : 0.f;
        const float uni = 1.f / 1024.f;   // reference: all-masked row -> uniform
        if (sub == 0) sInv[r] = any ? invl : 1.f;

        float4* rowA = gA ? reinterpret_cast<float4*>(gA + (size_t)r * S_) : nullptr;
        #pragma unroll 4
        for (int j = 0; j < 16; j++) {
            int i4 = sub + j * 16;
            float4 p = rowS[i4];
            float4 o;
            if (any) { o.x = p.x * invl; o.y = p.y * invl; o.z = p.z * invl; o.w = p.w * invl; }
            else     { o.x = o.y = o.z = o.w = uni; rowS[i4] = o; }  // fix sS for PV
            if (rowA) rowA[i4] = o;    // normalized attn output
        }
    }
    // (PV loop's wait+syncthreads orders softmax writes before cross-warp reads)

    // ---- P(unnorm) @ V with 2m x 4n x 2k warp split ----
    // wm = warp>>3 (rows qb..), wnv = (warp>>1)&3 (cols wnv*16..+15), wk2 = warp&1 (half-chunk)
    const int wnv = (warp >> 1) & 3;
    const int wk2 = warp & 1;
    float o0[4] = {0.f, 0.f, 0.f, 0.f};
    float o1[4] = {0.f, 0.f, 0.f, 0.f};
    for (int c = 0; c < NCH; c++) {
        CP_WAIT1();
        __syncthreads();
        const float* sV = sKV + (c & 1) * KC * PADV;
        const int kbase = wk2 * 64;
        #pragma unroll
        for (int ks = 0; ks < 8; ks++) {
            unsigned a[4];
            int r0 = qb + (lane >> 2);
            int kc = c * KC + kbase + ks * 8 + (lane & 3);
            a[0] = f2tf(sS[r0 * PADS + kc]);
            a[1] = f2tf(sS[(r0 + 8) * PADS + kc]);
            a[2] = f2tf(sS[r0 * PADS + kc + 4]);
            a[3] = f2tf(sS[(r0 + 8) * PADS + kc + 4]);
            int key = kbase + ks * 8 + (lane & 3);
            int dc0 = wnv * 16 + (lane >> 2);
            unsigned b0 = f2tf(sV[key * PADV + dc0]);
            unsigned b1 = f2tf(sV[(key + 4) * PADV + dc0]);
            mma8(o0, a, b0, b1);
            unsigned b2 = f2tf(sV[key * PADV + dc0 + 8]);
            unsigned b3 = f2tf(sV[(key + 4) * PADV + dc0 + 8]);
            mma8(o1, a, b2, b3);
        }
        __syncthreads();
        if (c + 2 < NCH) {
            const float* src = gV + (size_t)(c + 2) * KC * D_;
            float* dst = sKV + (c & 1) * KC * PADV;
            #pragma unroll
            for (int j = 0; j < 4; j++) {
                int f = j * NTHREADS + tid;
                int row = f >> 4, c4 = f & 15;
                cpasync16(dst + row * PADV + c4 * 4, src + row * D_ + c4 * 4);
            }
        }
        CP_COMMIT();
    }

    // ---- 2-way k reduction via smem (reuse sQ region), scale by invl, write O ----
    {
        float* red = sQ;   // 8 tiles * 256 floats = 2048 <= SZ_Q
        int tile = (warp >> 1);          // (wm*4 + wnv), 0..7
        if (wk2 == 1) {
            float* dst = red + tile * 256 + lane * 8;
            dst[0] = o0[0]; dst[1] = o0[1]; dst[2] = o0[2]; dst[3] = o0[3];
            dst[4] = o1[0]; dst[5] = o1[1]; dst[6] = o1[2]; dst[7] = o1[3];
        }
        __syncthreads();
        if (wk2 == 0) {
            const float* src = red + tile * 256 + lane * 8;
            o0[0] += src[0]; o0[1] += src[1]; o0[2] += src[2]; o0[3] += src[3];
            o1[0] += src[4]; o1[1] += src[5]; o1[2] += src[6]; o1[3] += src[7];

            int r0  = qb + (lane >> 2);
            float inv0 = sInv[r0];
            float inv1 = sInv[r0 + 8];
            int col = wnv * 16 + 2 * (lane & 3);
            *reinterpret_cast<float2*>(&gO[(size_t)r0 * D_ + col]) =
                make_float2(o0[0] * inv0, o0[1] * inv0);
            *reinterpret_cast<float2*>(&gO[(size_t)(r0 + 8) * D_ + col]) =
                make_float2(o0[2] * inv1, o0[3] * inv1);
            *reinterpret_cast<float2*>(&gO[(size_t)r0 * D_ + col + 8]) =
                make_float2(o1[0] * inv0, o1[1] * inv0);
            *reinterpret_cast<float2*>(&gO[(size_t)(r0 + 8) * D_ + col + 8]) =
                make_float2(o1[2] * inv1, o1[3] * inv1);
        }
    }
}

extern "C" void kernel_launch(void* const* d_in, const int* in_sizes, int n_in,
                              void* d_out, int out_size)
{
    const float* q    = (const float*)d_in[0];
    const float* k    = (const float*)d_in[1];
    const float* v    = (const float*)d_in[2];
    const int*   mask = (const int*)d_in[3];
    float* out = (float*)d_out;

    const size_t out_elems  = (size_t)BH_ * S_ * D_;   //  4,194,304
    const size_t attn_elems = (size_t)BH_ * S_ * S_;   // 67,108,864
    float* attn = ((size_t)out_size >= out_elems + attn_elems) ? (out + out_elems) : nullptr;

    cudaFuncSetAttribute(attn_kernel, cudaFuncAttributeMaxDynamicSharedMemorySize, SMEM_BYTES);

    dim3 grid(S_ / QT, BH_);
    attn_kernel<<<grid, NTHREADS, SMEM_BYTES>>>(q, k, v, mask, out, attn);
}

// round 6
// speedup vs baseline: 1.2321x; 1.0758x over previous
#include <cuda_runtime.h>
#include <cstdint>

// Problem constants
#define BH_  64
#define S_   1024
#define D_   64
#define QT   32      // queries per CTA
#define KC   128     // keys per pipeline chunk
#define NCH  (S_/KC) // 8 chunks
#define NTHREADS 512

// smem strides (floats)
#define PADK 68      // K/Q rows: QK B-loads conflict-free
#define PADV 72      // V rows:   PV B-loads conflict-free
#define PADS 1028    // score rows: PV A-loads conflict-free
#define RSTR 68      // PV reduction partial row stride
#define RPART (16*RSTR)  // floats per partial tile (1088)

// smem layout (float offsets)
#define OFF_Q  0
#define SZ_Q   (QT*PADK)            // 2176
#define OFF_KV (OFF_Q + SZ_Q)
#define SZ_KV  (2*KC*PADV)          // 18432
#define OFF_S  (OFF_KV + SZ_KV)
#define SZ_S   (QT*PADS)            // 32896 (also reused for 16*RPART=17408 reduction)
#define OFF_M  (OFF_S + SZ_S)       // mask: 1024 ints
#define OFF_INV (OFF_M + S_)        // 32 floats
#define SMEM_FLOATS (OFF_INV + 32)
#define SMEM_BYTES  (SMEM_FLOATS * 4)   // ~218 KB < 227 KB

#define NEGB (-1e30f)

__device__ __forceinline__ unsigned f2tf(float x) {
    unsigned r;
    asm("cvt.rna.tf32.f32 %0, %1;" : "=r"(r) : "f"(x));
    return r;
}

__device__ __forceinline__ void mma8(float* c, const unsigned* a, unsigned b0, unsigned b1) {
    asm volatile(
        "mma.sync.aligned.m16n8k8.row.col.f32.tf32.tf32.f32 "
        "{%0,%1,%2,%3},{%4,%5,%6,%7},{%8,%9},{%0,%1,%2,%3};\n"
        : "+f"(c[0]), "+f"(c[1]), "+f"(c[2]), "+f"(c[3])
        : "r"(a[0]), "r"(a[1]), "r"(a[2]), "r"(a[3]), "r"(b0), "r"(b1));
}

__device__ __forceinline__ void cpasync16(float* smem_dst, const float* gsrc) {
    unsigned d = (unsigned)__cvta_generic_to_shared(smem_dst);
    asm volatile("cp.async.cg.shared.global [%0],[%1],16;\n" :: "r"(d), "l"(gsrc));
}
#define CP_COMMIT() asm volatile("cp.async.commit_group;\n" ::: "memory")
#define CP_WAIT0()  asm volatile("cp.async.wait_group 0;\n" ::: "memory")

__global__ void __launch_bounds__(NTHREADS, 1)
attn_kernel(const float* __restrict__ Q, const float* __restrict__ K,
            const float* __restrict__ V, const int* __restrict__ M,
            float* __restrict__ Out, float* __restrict__ Attn)
{
    extern __shared__ float sm[];
    float* sQ   = sm + OFF_Q;
    float* sKV  = sm + OFF_KV;   // two buffers of KC*PADV floats each
    float* sS   = sm + OFF_S;    // 32 x 1024 scores/probs (padded stride); later: reduction
    int*   sM   = (int*)(sm + OFF_M);
    float* sInv = sm + OFF_INV;

    const int bh   = blockIdx.y;
    const int q0   = blockIdx.x * QT;
    const int tid  = threadIdx.x;
    const int lane = tid & 31;
    const int warp = tid >> 5;   // 0..15

    const float* gQ = Q + ((size_t)bh * S_ + q0) * D_;
    const float* gK = K + (size_t)bh * S_ * D_;
    const float* gV = V + (size_t)bh * S_ * D_;
    const int*   gM = M + bh * S_;
    float* gO = Out + ((size_t)bh * S_ + q0) * D_;
    float* gA = Attn ? (Attn + ((size_t)bh * S_ + q0) * S_) : nullptr;

    // ---- prologue: K chunk 0 via cp.async, then stage Q + mask ----
    {
        float* dst = sKV;   // slot 0, K layout (PADK)
        #pragma unroll
        for (int j = 0; j < 4; j++) {
            int f = j * NTHREADS + tid;
            int row = f >> 4, c4 = f & 15;
            cpasync16(dst + row * PADK + c4 * 4, gK + row * D_ + c4 * 4);
        }
        CP_COMMIT();
    }
    {
        int row = tid >> 4, c4 = tid & 15;    // 512 float4s exactly
        float4 val = reinterpret_cast<const float4*>(gQ)[row * (D_ / 4) + c4];
        *reinterpret_cast<float4*>(sQ + row * PADK + c4 * 4) = val;
    }
    for (int i = tid; i < S_ / 4; i += NTHREADS)
        reinterpret_cast<int4*>(sM)[i] = reinterpret_cast<const int4*>(gM)[i];

    CP_WAIT0();
    __syncthreads();   // K0, sQ, sM visible

    // ---- preload Q (A) fragments in tf32, reused for the whole kernel ----
    const int qb = (warp >> 3) * 16;   // m-tile rows qb..qb+15
    unsigned afr[8][4];
    #pragma unroll
    for (int ks = 0; ks < 8; ks++) {
        int r0 = qb + (lane >> 2);
        int c0 = (lane & 3) + ks * 8;
        afr[ks][0] = f2tf(sQ[r0 * PADK + c0]);
        afr[ks][1] = f2tf(sQ[(r0 + 8) * PADK + c0]);
        afr[ks][2] = f2tf(sQ[r0 * PADK + c0 + 4]);
        afr[ks][3] = f2tf(sQ[(r0 + 8) * PADK + c0 + 4]);
    }

    // ---- QK^T: single sync per chunk; mask applied at score write ----
    // Warp layout: wm = warp>>3 (rows), wn = warp&7 (keys wn*16..wn*16+15)
    const int wn = warp & 7;
    for (int c = 0; c < NCH; c++) {
        if (c) { CP_WAIT0(); __syncthreads(); }
        // prefetch: next K chunk, or V chunk 0 on the last iteration
        if (c + 1 < NCH) {
            const float* src = gK + (size_t)(c + 1) * KC * D_;
            float* dst = sKV + ((c + 1) & 1) * KC * PADV;
            #pragma unroll
            for (int j = 0; j < 4; j++) {
                int f = j * NTHREADS + tid;
                int row = f >> 4, c4 = f & 15;
                cpasync16(dst + row * PADK + c4 * 4, src + row * D_ + c4 * 4);
            }
        } else {
            // V chunk 0 into slot 0 (K chunk 6 fully consumed: covered by this iter's sync)
            float* dst = sKV;
            #pragma unroll
            for (int j = 0; j < 4; j++) {
                int f = j * NTHREADS + tid;
                int row = f >> 4, c4 = f & 15;
                cpasync16(dst + row * PADV + c4 * 4, gV + row * D_ + c4 * 4);
            }
        }
        CP_COMMIT();

        const float* sK = sKV + (c & 1) * KC * PADV;  // K layout (PADK stride)
        float acc[2][4];
        #pragma unroll
        for (int nt = 0; nt < 2; nt++) { acc[nt][0] = acc[nt][1] = acc[nt][2] = acc[nt][3] = 0.f; }

        #pragma unroll
        for (int ks = 0; ks < 8; ks++) {
            #pragma unroll
            for (int nt = 0; nt < 2; nt++) {
                int key = wn * 16 + nt * 8 + (lane >> 2);
                int d0  = (lane & 3) + ks * 8;
                unsigned b0 = f2tf(sK[key * PADK + d0]);
                unsigned b1 = f2tf(sK[key * PADK + d0 + 4]);
                mma8(acc[nt], afr[ks], b0, b1);
            }
        }
        #pragma unroll
        for (int nt = 0; nt < 2; nt++) {
            int col = c * KC + wn * 16 + nt * 8 + 2 * (lane & 3);
            int r0  = qb + (lane >> 2);
            int2 mk = *reinterpret_cast<const int2*>(&sM[col]);
            float s0 = mk.x ? acc[nt][0] : NEGB;
            float s1 = mk.y ? acc[nt][1] : NEGB;
            float s2 = mk.x ? acc[nt][2] : NEGB;
            float s3 = mk.y ? acc[nt][3] : NEGB;
            *reinterpret_cast<float2*>(&sS[r0 * PADS + col])       = make_float2(s0, s1);
            *reinterpret_cast<float2*>(&sS[(r0 + 8) * PADS + col]) = make_float2(s2, s3);
        }
    }
    __syncthreads();   // all scores in sS; slot1 (K7) free for V1 prefetch in PV iter 0

    // ---- softmax over 32 rows (16 lanes/row), no mask logic needed ----
    // masked entries are -1e30 -> exp2((s-mx)*C) = 0 exactly.
    // fully-masked row: all s equal -> p=1 everywhere -> attn = 1/1024 (matches reference).
    {
        const int r   = tid >> 4;
        const int sub = tid & 15;
        const float CEXP = 0.125f * 1.44269504088896340736f;  // (1/T)*log2(e)
        float4* rowS = reinterpret_cast<float4*>(sS + (size_t)r * PADS);

        float mx = NEGB;
        #pragma unroll 4
        for (int j = 0; j < 16; j++) {
            float4 s = rowS[sub + j * 16];
            mx = fmaxf(mx, fmaxf(fmaxf(s.x, s.y), fmaxf(s.z, s.w)));
        }
        mx = fmaxf(mx, __shfl_xor_sync(0xffffffffu, mx, 1));
        mx = fmaxf(mx, __shfl_xor_sync(0xffffffffu, mx, 2));
        mx = fmaxf(mx, __shfl_xor_sync(0xffffffffu, mx, 4));
        mx = fmaxf(mx, __shfl_xor_sync(0xffffffffu, mx, 8));

        float l = 0.f;
        #pragma unroll 4
        for (int j = 0; j < 16; j++) {
            int i4 = sub + j * 16;
            float4 s = rowS[i4];
            float4 p;
            p.x = exp2f((s.x - mx) * CEXP);
            p.y = exp2f((s.y - mx) * CEXP);
            p.z = exp2f((s.z - mx) * CEXP);
            p.w = exp2f((s.w - mx) * CEXP);
            rowS[i4] = p;              // unnormalized p kept for PV
            l += (p.x + p.y) + (p.z + p.w);
        }
        l += __shfl_xor_sync(0xffffffffu, l, 1);
        l += __shfl_xor_sync(0xffffffffu, l, 2);
        l += __shfl_xor_sync(0xffffffffu, l, 4);
        l += __shfl_xor_sync(0xffffffffu, l, 8);

        float invl = 1.f / l;          // l >= 1 always (max element contributes 1)
        if (sub == 0) sInv[r] = invl;

        if (gA) {
            float4* rowA = reinterpret_cast<float4*>(gA + (size_t)r * S_);
            #pragma unroll 4
            for (int j = 0; j < 16; j++) {
                int i4 = sub + j * 16;
                float4 p = rowS[i4];
                p.x *= invl; p.y *= invl; p.z *= invl; p.w *= invl;
                rowA[i4] = p;          // normalized attn
            }
        }
    }

    // ---- P(unnorm) @ V: 2m x 8k warp split (A-frags unique per warp) ----
    const int wk = warp & 7;     // key slice wk*16..+15 within each chunk
    float o[8][4];
    #pragma unroll
    for (int nt = 0; nt < 8; nt++) { o[nt][0] = o[nt][1] = o[nt][2] = o[nt][3] = 0.f; }

    for (int c = 0; c < NCH; c++) {
        CP_WAIT0();
        __syncthreads();   // V(c) visible; softmax writes visible (c==0); prior reads done
        if (c + 1 < NCH) {
            const float* src = gV + (size_t)(c + 1) * KC * D_;
            float* dst = sKV + ((c + 1) & 1) * KC * PADV;
            #pragma unroll
            for (int j = 0; j < 4; j++) {
                int f = j * NTHREADS + tid;
                int row = f >> 4, c4 = f & 15;
                cpasync16(dst + row * PADV + c4 * 4, src + row * D_ + c4 * 4);
            }
        }
        CP_COMMIT();

        const float* sV = sKV + (c & 1) * KC * PADV;
        const int kb = wk * 16;
        #pragma unroll
        for (int kk = 0; kk < 2; kk++) {
            unsigned a[4];
            int r0 = qb + (lane >> 2);
            int kc = c * KC + kb + kk * 8 + (lane & 3);
            a[0] = f2tf(sS[r0 * PADS + kc]);
            a[1] = f2tf(sS[(r0 + 8) * PADS + kc]);
            a[2] = f2tf(sS[r0 * PADS + kc + 4]);
            a[3] = f2tf(sS[(r0 + 8) * PADS + kc + 4]);
            int key = kb + kk * 8 + (lane & 3);
            int dc  = lane >> 2;
            #pragma unroll
            for (int nt = 0; nt < 8; nt++) {
                unsigned b0 = f2tf(sV[key * PADV + nt * 8 + dc]);
                unsigned b1 = f2tf(sV[(key + 4) * PADV + nt * 8 + dc]);
                mma8(o[nt], a, b0, b1);
            }
        }
    }

    // ---- 8-way k reduction through smem (reuse score region), fold invl, write O ----
    __syncthreads();   // all PV reads of sS done; safe to overwrite with partials
    {
        float* red = sS;
        float* base = red + warp * RPART;
        int r0 = lane >> 2;
        #pragma unroll
        for (int nt = 0; nt < 8; nt++) {
            int cc = nt * 8 + 2 * (lane & 3);
            *reinterpret_cast<float2*>(&base[r0 * RSTR + cc])       = make_float2(o[nt][0], o[nt][1]);
            *reinterpret_cast<float2*>(&base[(r0 + 8) * RSTR + cc]) = make_float2(o[nt][2], o[nt][3]);
        }
    }
    __syncthreads();
    {
        const float* red = sS;
        int r = tid >> 4, c4 = tid & 15;
        int wmr = r >> 4, row16 = r & 15;
        const float* pb = red + (size_t)(wmr * 8) * RPART + row16 * RSTR + c4 * 4;
        float4 acc4 = *reinterpret_cast<const float4*>(pb);
        #pragma unroll
        for (int k2 = 1; k2 < 8; k2++) {
            float4 t = *reinterpret_cast<const float4*>(pb + (size_t)k2 * RPART);
            acc4.x += t.x; acc4.y += t.y; acc4.z += t.z; acc4.w += t.w;
        }
        float inv = sInv[r];
        acc4.x *= inv; acc4.y *= inv; acc4.z *= inv; acc4.w *= inv;
        *reinterpret_cast<float4*>(&gO[(size_t)r * D_ + c4 * 4]) = acc4;
    }
}

extern "C" void kernel_launch(void* const* d_in, const int* in_sizes, int n_in,
                              void* d_out, int out_size)
{
    const float* q    = (const float*)d_in[0];
    const float* k    = (const float*)d_in[1];
    const float* v    = (const float*)d_in[2];
    const int*   mask = (const int*)d_in[3];
    float* out = (float*)d_out;

    const size_t out_elems  = (size_t)BH_ * S_ * D_;   //  4,194,304
    const size_t attn_elems = (size_t)BH_ * S_ * S_;   // 67,108,864
    float* attn = ((size_t)out_size >= out_elems + attn_elems) ? (out + out_elems) : nullptr;

    cudaFuncSetAttribute(attn_kernel, cudaFuncAttributeMaxDynamicSharedMemorySize, SMEM_BYTES);

    dim3 grid(S_ / QT, BH_);
    attn_kernel<<<grid, NTHREADS, SMEM_BYTES>>>(q, k, v, mask, out, attn);
}